// round 16
// baseline (speedup 1.0000x reference)
#include <cuda_runtime.h>
#include <cuda_fp16.h>
#include <math.h>
#include <stdint.h>

#define N_SRC 100000
#define N_DST 100000
#define NE    1600000
#define DIN   128
#define DOUT  128
#define SLOTS 64    // per-dst bucket capacity; P(deg>=64) < 1e-20 for Poisson(16)

// ---------------- scratch (static device globals; no allocs allowed) ----------------
__device__ __half    g_nh[(size_t)N_SRC * DOUT];          // relu(h_src @ Q^T + b), fp16
__device__ __half    g_aggh[(size_t)N_DST * DOUT];        // aggregated + normalized, fp16
__device__ __half    g_hh[(size_t)N_DST * DOUT];          // h_dst converted to fp16
__device__ __half    g_qh[128 * 128];                     // Q_w fp16
__device__ __half    g_wh[128 * 256];                     // W_w fp16
__device__ int       g_cur[N_DST];                        // per-dst fill count
__device__ uint64_t  g_edge[(size_t)N_DST * SLOTS];       // slotted (src lo, w_f32 hi)

// ---------------- fp16 MMA + LDSM helpers ----------------
__device__ __forceinline__ uint32_t pack_h2(float x, float y) {
    __half2 h = __floats2half2_rn(x, y);
    return *(uint32_t*)&h;
}

__device__ __forceinline__ void mma_f16(float* d, const uint32_t* a,
                                        uint32_t b0, uint32_t b1, const float* c) {
    asm volatile(
        "mma.sync.aligned.m16n8k16.row.col.f32.f16.f16.f32 "
        "{%0,%1,%2,%3}, {%4,%5,%6,%7}, {%8,%9}, {%10,%11,%12,%13};\n"
        : "=f"(d[0]), "=f"(d[1]), "=f"(d[2]), "=f"(d[3])
        : "r"(a[0]), "r"(a[1]), "r"(a[2]), "r"(a[3]),
          "r"(b0), "r"(b1),
          "f"(c[0]), "f"(c[1]), "f"(c[2]), "f"(c[3]));
}

__device__ __forceinline__ void ldsm_x4(uint32_t* r, uint32_t saddr) {
    asm volatile("ldmatrix.sync.aligned.m8n8.x4.shared.b16 {%0,%1,%2,%3}, [%4];"
                 : "=r"(r[0]), "=r"(r[1]), "=r"(r[2]), "=r"(r[3]) : "r"(saddr));
}

#define GEMM_SMEM_WORDS(K) (128 * ((K) == 128 ? 68 : 132) + 2 * 128 * 20 + 256)

// ---------------- weight / h_dst fp16 pre-conversion ----------------
__global__ void __launch_bounds__(256)
convert_w(const float* __restrict__ Qw, const float* __restrict__ Ww)
{
    int i = blockIdx.x * 256 + threadIdx.x;   // float4 index
    if (i < 4096) {                           // Qw: 16384 floats
        float4 v = ((const float4*)Qw)[i];
        uint2 o = make_uint2(pack_h2(v.x, v.y), pack_h2(v.z, v.w));
        ((uint2*)g_qh)[i] = o;
    } else if (i < 4096 + 8192) {             // Ww: 32768 floats
        int j = i - 4096;
        float4 v = ((const float4*)Ww)[j];
        uint2 o = make_uint2(pack_h2(v.x, v.y), pack_h2(v.z, v.w));
        ((uint2*)g_wh)[j] = o;
    }
}

__global__ void __launch_bounds__(256)
convert_h(const float* __restrict__ hdst)
{
    size_t i = (size_t)blockIdx.x * 256 + threadIdx.x;   // float4 index
    if (i >= (size_t)N_DST * 32) return;
    float4 v = ((const float4*)hdst)[i];
    uint2 o = make_uint2(pack_h2(v.x, v.y), pack_h2(v.z, v.w));
    ((uint2*)g_hh)[i] = o;
}

// ---------------- tensor-core GEMM: C[M,128] = relu(A @ B^T + bias) --------------
// B pre-converted fp16 (g_qh / g_wh): staging is pure 16B copies, no cvt.
// FUSE: A = [aggh | g_hh], both fp16 -> branch-free 8B loads, no cvt.
template<int K, bool FUSE, bool NORM, bool HALF_OUT>
__global__ void __launch_bounds__(256, 2)
gemm_tc(const float* __restrict__ A,
        const __half* __restrict__ aggh,
        const __half* __restrict__ hh,
        const __half* __restrict__ Bh,    // [128, K] fp16
        const float* __restrict__ bias,   // [128]
        void* __restrict__ Cv, int M)
{
    constexpr int SB  = (K == 128) ? 68 : 132;
    constexpr int NCH = K / 32;

    extern __shared__ uint32_t sm[];
    uint32_t* Bs = sm;                          // [128][SB]
    uint32_t* As = sm + 128 * SB;               // [2][128][20]
    float* rowsq = (float*)(sm + 128 * SB + 2 * 128 * 20);
    float* rinv  = rowsq + 128;

    const int t     = threadIdx.x;
    const int lane  = t & 31;
    const int w     = t >> 5;
    const int warpM = w >> 1;
    const int warpN = w & 1;
    const int row0  = blockIdx.x * 128;
    const int gid   = lane >> 2;
    const int tig   = lane & 3;

    // ---- stage B fully (once), fp16 source: 16B copies ----
    #pragma unroll
    for (int i = t; i < 128 * (K / 8); i += 256) {
        int row = i / (K / 8);
        int q   = i % (K / 8);
        uint4 vb = *(const uint4*)(Bh + (size_t)row * K + q * 8);
        Bs[row * SB + q * 4 + 0] = vb.x;
        Bs[row * SB + q * 4 + 1] = vb.y;
        Bs[row * SB + q * 4 + 2] = vb.z;
        Bs[row * SB + q * 4 + 3] = vb.w;
    }

    const int prow = t >> 3;
    const int pq   = t & 7;

    uint2  pu[4];     // FUSE path (fp16 bits)
    float4 pa[4];     // non-FUSE path (fp32)
    auto loadA = [&](int c) {
        #pragma unroll
        for (int i = 0; i < 4; i++) {
            int row = prow + i * 32;
            int kk  = c * 32 + pq * 4;
            int gr  = row0 + row;
            if (FUSE) {
                uint2 r = make_uint2(0u, 0u);
                if (gr < M) {
                    const __half* p = (kk < 128)
                        ? (aggh + (size_t)gr * 128 + kk)
                        : (hh   + (size_t)gr * 128 + (kk - 128));
                    r = *(const uint2*)p;
                }
                pu[i] = r;
            } else {
                float4 va = make_float4(0.f, 0.f, 0.f, 0.f);
                if (gr < M) va = *(const float4*)(A + (size_t)gr * K + kk);
                pa[i] = va;
            }
        }
    };
    auto storeA = [&](int c) {
        uint32_t* dstb = As + (c & 1) * (128 * 20);
        #pragma unroll
        for (int i = 0; i < 4; i++) {
            int row = prow + i * 32;
            if (FUSE) {
                dstb[row * 20 + pq * 2 + 0] = pu[i].x;
                dstb[row * 20 + pq * 2 + 1] = pu[i].y;
            } else {
                dstb[row * 20 + pq * 2 + 0] = pack_h2(pa[i].x, pa[i].y);
                dstb[row * 20 + pq * 2 + 1] = pack_h2(pa[i].z, pa[i].w);
            }
        }
    };

    // ---- LDSM base addresses ----
    const uint32_t AsB = (uint32_t)__cvta_generic_to_shared(As);
    const uint32_t BsB = (uint32_t)__cvta_generic_to_shared(Bs);
    const uint32_t a_base = AsB +
        (((warpM * 32 + (lane & 15)) * 20 + (lane >> 4) * 4) << 2);
    uint32_t b_base[4];
    #pragma unroll
    for (int p = 0; p < 4; p++)
        b_base[p] = BsB +
            (((warpN * 64 + p * 16 + ((lane >> 4) << 3) + (lane & 7)) * SB +
              ((lane >> 3) & 1) * 4) << 2);

    float acc[2][8][4];
    #pragma unroll
    for (int mt = 0; mt < 2; mt++)
        #pragma unroll
        for (int nt = 0; nt < 8; nt++)
            #pragma unroll
            for (int r = 0; r < 4; r++) acc[mt][nt][r] = 0.f;

    loadA(0);

    #pragma unroll
    for (int c = 0; c < NCH; c++) {
        storeA(c);
        __syncthreads();
        if (c + 1 < NCH) loadA(c + 1);

        const uint32_t abuf = a_base + ((c & 1) * (128 * 20) << 2);
        #pragma unroll
        for (int ks = 0; ks < 2; ks++) {
            uint32_t a[2][4], bf[4][4];
            ldsm_x4(a[0], abuf + (ks * 8 << 2));
            ldsm_x4(a[1], abuf + ((16 * 20 + ks * 8) << 2));
            #pragma unroll
            for (int p = 0; p < 4; p++)
                ldsm_x4(bf[p], b_base[p] + ((c * 16 + ks * 8) << 2));
            #pragma unroll
            for (int mt = 0; mt < 2; mt++)
                #pragma unroll
                for (int nt = 0; nt < 8; nt++)
                    mma_f16(acc[mt][nt], a[mt],
                            bf[nt >> 1][(nt & 1) * 2], bf[nt >> 1][(nt & 1) * 2 + 1],
                            acc[mt][nt]);
        }
    }
    __syncthreads();

    #pragma unroll
    for (int nt = 0; nt < 8; nt++) {
        int cb = warpN * 64 + nt * 8 + 2 * tig;
        float b0 = __ldg(bias + cb);
        float b1 = __ldg(bias + cb + 1);
        #pragma unroll
        for (int mt = 0; mt < 2; mt++) {
            acc[mt][nt][0] = fmaxf(acc[mt][nt][0] + b0, 0.f);
            acc[mt][nt][1] = fmaxf(acc[mt][nt][1] + b1, 0.f);
            acc[mt][nt][2] = fmaxf(acc[mt][nt][2] + b0, 0.f);
            acc[mt][nt][3] = fmaxf(acc[mt][nt][3] + b1, 0.f);
        }
    }

    if (NORM) {
        float* C = (float*)Cv;
        if (t < 128) rowsq[t] = 0.f;
        __syncthreads();
        #pragma unroll
        for (int mt = 0; mt < 2; mt++) {
            float sA = 0.f, sB = 0.f;
            #pragma unroll
            for (int nt = 0; nt < 8; nt++) {
                sA = fmaf(acc[mt][nt][0], acc[mt][nt][0], sA);
                sA = fmaf(acc[mt][nt][1], acc[mt][nt][1], sA);
                sB = fmaf(acc[mt][nt][2], acc[mt][nt][2], sB);
                sB = fmaf(acc[mt][nt][3], acc[mt][nt][3], sB);
            }
            sA += __shfl_xor_sync(0xffffffffu, sA, 1);
            sA += __shfl_xor_sync(0xffffffffu, sA, 2);
            sB += __shfl_xor_sync(0xffffffffu, sB, 1);
            sB += __shfl_xor_sync(0xffffffffu, sB, 2);
            if (tig == 0) {
                int lr = warpM * 32 + mt * 16 + gid;
                atomicAdd(&rowsq[lr], sA);
                atomicAdd(&rowsq[lr + 8], sB);
            }
        }
        __syncthreads();
        if (t < 128) {
            float nrm = sqrtf(rowsq[t]);
            rinv[t] = (nrm > 0.f) ? (1.f / nrm) : 1.f;
        }
        __syncthreads();
        #pragma unroll
        for (int mt = 0; mt < 2; mt++) {
            int lrA = warpM * 32 + mt * 16 + gid;
            int rA  = row0 + lrA;
            float sa = rinv[lrA];
            float sb = rinv[lrA + 8];
            #pragma unroll
            for (int nt = 0; nt < 8; nt++) {
                int cb = warpN * 64 + nt * 8 + 2 * tig;
                if (rA < M) {
                    float2 v = make_float2(acc[mt][nt][0] * sa, acc[mt][nt][1] * sa);
                    *(float2*)(C + (size_t)rA * 128 + cb) = v;
                }
                if (rA + 8 < M) {
                    float2 v = make_float2(acc[mt][nt][2] * sb, acc[mt][nt][3] * sb);
                    *(float2*)(C + (size_t)(rA + 8) * 128 + cb) = v;
                }
            }
        }
    } else {
        #pragma unroll
        for (int mt = 0; mt < 2; mt++) {
            int rA = row0 + warpM * 32 + mt * 16 + gid;
            #pragma unroll
            for (int nt = 0; nt < 8; nt++) {
                int cb = warpN * 64 + nt * 8 + 2 * tig;
                if (HALF_OUT) {
                    __half* C = (__half*)Cv;
                    if (rA < M) {
                        __half2 v = __floats2half2_rn(acc[mt][nt][0], acc[mt][nt][1]);
                        *(__half2*)(C + (size_t)rA * 128 + cb) = v;
                    }
                    if (rA + 8 < M) {
                        __half2 v = __floats2half2_rn(acc[mt][nt][2], acc[mt][nt][3]);
                        *(__half2*)(C + (size_t)(rA + 8) * 128 + cb) = v;
                    }
                } else {
                    float* C = (float*)Cv;
                    if (rA < M) {
                        float2 v = make_float2(acc[mt][nt][0], acc[mt][nt][1]);
                        *(float2*)(C + (size_t)rA * 128 + cb) = v;
                    }
                    if (rA + 8 < M) {
                        float2 v = make_float2(acc[mt][nt][2], acc[mt][nt][3]);
                        *(float2*)(C + (size_t)(rA + 8) * 128 + cb) = v;
                    }
                }
            }
        }
    }
}

// ---------------- slotted bucketing: one pass, no hist/scan ----------------
__global__ void __launch_bounds__(256)
bucket_kernel(const int* __restrict__ src,
              const int* __restrict__ dst,
              const float* __restrict__ w)
{
    int i = blockIdx.x * 256 + threadIdx.x;
    if (i * 4 >= NE) return;
    int4   s4 = ((const int4*)src)[i];
    int4   d4 = ((const int4*)dst)[i];
    float4 w4 = ((const float4*)w)[i];
    int p0 = atomicAdd(&g_cur[d4.x], 1);
    int p1 = atomicAdd(&g_cur[d4.y], 1);
    int p2 = atomicAdd(&g_cur[d4.z], 1);
    int p3 = atomicAdd(&g_cur[d4.w], 1);
    if (p0 < SLOTS) g_edge[(size_t)d4.x * SLOTS + p0] =
        (uint64_t)(uint32_t)s4.x | ((uint64_t)__float_as_uint(w4.x) << 32);
    if (p1 < SLOTS) g_edge[(size_t)d4.y * SLOTS + p1] =
        (uint64_t)(uint32_t)s4.y | ((uint64_t)__float_as_uint(w4.y) << 32);
    if (p2 < SLOTS) g_edge[(size_t)d4.z * SLOTS + p2] =
        (uint64_t)(uint32_t)s4.z | ((uint64_t)__float_as_uint(w4.z) << 32);
    if (p3 < SLOTS) g_edge[(size_t)d4.w * SLOTS + p3] =
        (uint64_t)(uint32_t)s4.w | ((uint64_t)__float_as_uint(w4.w) << 32);
}

// ---------------- aggregation: warp per dst, fp16 gather, fp16 output -----------
__global__ void __launch_bounds__(256)
aggregate_kernel()
{
    int d = blockIdx.x * 8 + (threadIdx.x >> 5);
    if (d >= N_DST) return;
    int lane = threadIdx.x & 31;
    const uint64_t* eb = g_edge + (size_t)d * SLOTS;
    int cnt = g_cur[d];
    if (cnt > SLOTS) cnt = SLOTS;

    float4 acc = make_float4(0.f, 0.f, 0.f, 0.f);
    float ws = 0.f;
    int i = 0;
    for (; i + 3 < cnt; i += 4) {
        uint64_t e0 = eb[i],     e1 = eb[i + 1];
        uint64_t e2 = eb[i + 2], e3 = eb[i + 3];
        int   s0 = (int)(uint32_t)e0, s1 = (int)(uint32_t)e1;
        int   s2 = (int)(uint32_t)e2, s3 = (int)(uint32_t)e3;
        float w0 = __uint_as_float((uint32_t)(e0 >> 32));
        float w1 = __uint_as_float((uint32_t)(e1 >> 32));
        float w2 = __uint_as_float((uint32_t)(e2 >> 32));
        float w3 = __uint_as_float((uint32_t)(e3 >> 32));
        uint2 r0 = ((const uint2*)(g_nh + (size_t)s0 * 128))[lane];
        uint2 r1 = ((const uint2*)(g_nh + (size_t)s1 * 128))[lane];
        uint2 r2 = ((const uint2*)(g_nh + (size_t)s2 * 128))[lane];
        uint2 r3 = ((const uint2*)(g_nh + (size_t)s3 * 128))[lane];
        float2 a0 = __half22float2(*(__half2*)&r0.x), b0 = __half22float2(*(__half2*)&r0.y);
        float2 a1 = __half22float2(*(__half2*)&r1.x), b1 = __half22float2(*(__half2*)&r1.y);
        float2 a2 = __half22float2(*(__half2*)&r2.x), b2 = __half22float2(*(__half2*)&r2.y);
        float2 a3 = __half22float2(*(__half2*)&r3.x), b3 = __half22float2(*(__half2*)&r3.y);
        acc.x = fmaf(a0.x, w0, acc.x); acc.y = fmaf(a0.y, w0, acc.y);
        acc.z = fmaf(b0.x, w0, acc.z); acc.w = fmaf(b0.y, w0, acc.w);
        acc.x = fmaf(a1.x, w1, acc.x); acc.y = fmaf(a1.y, w1, acc.y);
        acc.z = fmaf(b1.x, w1, acc.z); acc.w = fmaf(b1.y, w1, acc.w);
        acc.x = fmaf(a2.x, w2, acc.x); acc.y = fmaf(a2.y, w2, acc.y);
        acc.z = fmaf(b2.x, w2, acc.z); acc.w = fmaf(b2.y, w2, acc.w);
        acc.x = fmaf(a3.x, w3, acc.x); acc.y = fmaf(a3.y, w3, acc.y);
        acc.z = fmaf(b3.x, w3, acc.z); acc.w = fmaf(b3.y, w3, acc.w);
        ws += (w0 + w1) + (w2 + w3);
    }
    for (; i < cnt; i++) {
        uint64_t e0 = eb[i];
        int   s0 = (int)(uint32_t)e0;
        float w0 = __uint_as_float((uint32_t)(e0 >> 32));
        uint2 r0 = ((const uint2*)(g_nh + (size_t)s0 * 128))[lane];
        float2 a0 = __half22float2(*(__half2*)&r0.x), b0 = __half22float2(*(__half2*)&r0.y);
        acc.x = fmaf(a0.x, w0, acc.x); acc.y = fmaf(a0.y, w0, acc.y);
        acc.z = fmaf(b0.x, w0, acc.z); acc.w = fmaf(b0.y, w0, acc.w);
        ws += w0;
    }
    float inv = 1.f / fmaxf(ws, 1.f);
    uint2 o;
    o.x = pack_h2(acc.x * inv, acc.y * inv);
    o.y = pack_h2(acc.z * inv, acc.w * inv);
    ((uint2*)(g_aggh + (size_t)d * 128))[lane] = o;
}

extern "C" void kernel_launch(void* const* d_in, const int* in_sizes, int n_in,
                              void* d_out, int out_size)
{
    const float* h_src   = (const float*)d_in[0];
    const float* h_dst   = (const float*)d_in[1];
    const float* weights = (const float*)d_in[2];
    const float* Qw      = (const float*)d_in[3];
    const float* Qb      = (const float*)d_in[4];
    const float* Ww      = (const float*)d_in[5];
    const float* Wb      = (const float*)d_in[6];
    const int*   src     = (const int*)d_in[7];
    const int*   dst     = (const int*)d_in[8];
    float*       out     = (float*)d_out;

    const int smem1 = GEMM_SMEM_WORDS(128) * 4;
    const int smem2 = GEMM_SMEM_WORDS(256) * 4;

    static void *p_nh = nullptr, *p_aggh = nullptr, *p_hh = nullptr;
    static void *p_qh = nullptr, *p_wh = nullptr;
    static int  *p_cur = nullptr;
    static cudaStream_t s2 = nullptr;
    static cudaEvent_t ev_fork = nullptr, ev_g1 = nullptr, ev_join = nullptr;
    if (!p_nh) {
        cudaGetSymbolAddress(&p_nh,          g_nh);
        cudaGetSymbolAddress(&p_aggh,        g_aggh);
        cudaGetSymbolAddress(&p_hh,          g_hh);
        cudaGetSymbolAddress(&p_qh,          g_qh);
        cudaGetSymbolAddress(&p_wh,          g_wh);
        cudaGetSymbolAddress((void**)&p_cur, g_cur);
        cudaFuncSetAttribute(gemm_tc<128, false, false, true>,
                             cudaFuncAttributeMaxDynamicSharedMemorySize, smem1);
        cudaFuncSetAttribute(gemm_tc<256, true, true, false>,
                             cudaFuncAttributeMaxDynamicSharedMemorySize, smem2);
        cudaStreamCreateWithFlags(&s2, cudaStreamNonBlocking);
        cudaEventCreateWithFlags(&ev_fork, cudaEventDisableTiming);
        cudaEventCreateWithFlags(&ev_g1,   cudaEventDisableTiming);
        cudaEventCreateWithFlags(&ev_join, cudaEventDisableTiming);
    }

    // ---- fork: slotted bucketing on s2, weight-convert + gemm1 on default ----
    cudaEventRecord(ev_fork, 0);
    cudaStreamWaitEvent(s2, ev_fork, 0);

    cudaMemsetAsync(p_cur, 0, N_DST * sizeof(int), s2);
    bucket_kernel<<<(NE / 4 + 255) / 256, 256, 0, s2>>>(src, dst, weights);

    convert_w<<<48, 256>>>(Qw, Ww);
    gemm_tc<128, false, false, true><<<(N_SRC + 127) / 128, 256, smem1>>>(
        h_src, nullptr, nullptr, (const __half*)p_qh, Qb, p_nh, N_SRC);
    cudaEventRecord(ev_g1, 0);

    // s0: convert h_dst -> fp16 (needed only by gemm2); overlaps aggregate on s2
    convert_h<<<(N_DST * 32 + 255) / 256, 256>>>(h_dst);

    // ---- s2: aggregate needs g_nh + buckets ----
    cudaStreamWaitEvent(s2, ev_g1, 0);
    aggregate_kernel<<<(N_DST + 7) / 8, 256, 0, s2>>>();
    cudaEventRecord(ev_join, s2);

    // gemm2 on default stream (ordered after convert_h) after aggregate
    cudaStreamWaitEvent(0, ev_join, 0);
    gemm_tc<256, true, true, false><<<(N_DST + 127) / 128, 256, smem2>>>(
        nullptr, (const __half*)p_aggh, (const __half*)p_hh,
        (const __half*)p_wh, Wb, out, N_DST);
}

// round 17
// speedup vs baseline: 1.0882x; 1.0882x over previous
#include <cuda_runtime.h>
#include <cuda_fp16.h>
#include <math.h>
#include <stdint.h>

#define N_SRC 100000
#define N_DST 100000
#define NE    1600000
#define DIN   128
#define DOUT  128
#define SLOTS 64    // per-dst bucket capacity; P(deg>=64) < 1e-20 for Poisson(16)
#define GBLK  296   // persistent grid: 148 SMs x 2 CTAs = one wave

// ---------------- scratch (static device globals; no allocs allowed) ----------------
__device__ __half    g_nh[(size_t)N_SRC * DOUT];          // relu(h_src @ Q^T + b), fp16
__device__ __half    g_aggh[(size_t)N_DST * DOUT];        // aggregated + normalized, fp16
__device__ __half    g_qh[128 * 128];                     // Q_w fp16
__device__ __half    g_wh[128 * 256];                     // W_w fp16
__device__ int       g_cur[N_DST];                        // per-dst fill count
__device__ uint64_t  g_edge[(size_t)N_DST * SLOTS];       // slotted (src lo, w_f32 hi)

// ---------------- fp16 MMA + LDSM helpers ----------------
__device__ __forceinline__ uint32_t pack_h2(float x, float y) {
    __half2 h = __floats2half2_rn(x, y);
    return *(uint32_t*)&h;
}

__device__ __forceinline__ void mma_f16(float* d, const uint32_t* a,
                                        uint32_t b0, uint32_t b1, const float* c) {
    asm volatile(
        "mma.sync.aligned.m16n8k16.row.col.f32.f16.f16.f32 "
        "{%0,%1,%2,%3}, {%4,%5,%6,%7}, {%8,%9}, {%10,%11,%12,%13};\n"
        : "=f"(d[0]), "=f"(d[1]), "=f"(d[2]), "=f"(d[3])
        : "r"(a[0]), "r"(a[1]), "r"(a[2]), "r"(a[3]),
          "r"(b0), "r"(b1),
          "f"(c[0]), "f"(c[1]), "f"(c[2]), "f"(c[3]));
}

__device__ __forceinline__ void ldsm_x4(uint32_t* r, uint32_t saddr) {
    asm volatile("ldmatrix.sync.aligned.m8n8.x4.shared.b16 {%0,%1,%2,%3}, [%4];"
                 : "=r"(r[0]), "=r"(r[1]), "=r"(r[2]), "=r"(r[3]) : "r"(saddr));
}

#define GEMM_SMEM_WORDS(K) (128 * ((K) == 128 ? 68 : 132) + 2 * 128 * 20 + 256)

// ---------------- weight fp16 pre-conversion (tiny, runs in fork) ----------------
__global__ void __launch_bounds__(256)
convert_w(const float* __restrict__ Qw, const float* __restrict__ Ww)
{
    int i = blockIdx.x * 256 + threadIdx.x;   // float4 index
    if (i < 4096) {
        float4 v = ((const float4*)Qw)[i];
        ((uint2*)g_qh)[i] = make_uint2(pack_h2(v.x, v.y), pack_h2(v.z, v.w));
    } else if (i < 4096 + 8192) {
        int j = i - 4096;
        float4 v = ((const float4*)Ww)[j];
        ((uint2*)g_wh)[j] = make_uint2(pack_h2(v.x, v.y), pack_h2(v.z, v.w));
    }
}

// ---------------- persistent tensor-core GEMM: C[M,128] = relu(A @ B^T + bias) ----
// B (fp16) staged ONCE per persistent block; grid-stride loop over 128-row tiles.
// FUSE: A = [aggh(fp16) | hdst(fp32->cvt)].  NORM: fused row L2 norm.
template<int K, bool FUSE, bool NORM, bool HALF_OUT>
__global__ void __launch_bounds__(256, 2)
gemm_tc(const float* __restrict__ A,
        const __half* __restrict__ aggh,
        const float* __restrict__ hdst,
        const __half* __restrict__ Bh,    // [128, K] fp16
        const float* __restrict__ bias,   // [128]
        void* __restrict__ Cv, int M)
{
    constexpr int SB  = (K == 128) ? 68 : 132;
    constexpr int NCH = K / 32;

    extern __shared__ uint32_t sm[];
    uint32_t* Bs = sm;                          // [128][SB]
    uint32_t* As = sm + 128 * SB;               // [2][128][20]
    float* rowsq = (float*)(sm + 128 * SB + 2 * 128 * 20);
    float* rinv  = rowsq + 128;

    const int t     = threadIdx.x;
    const int lane  = t & 31;
    const int w     = t >> 5;
    const int warpM = w >> 1;
    const int warpN = w & 1;
    const int gid   = lane >> 2;
    const int tig   = lane & 3;

    // ---- stage B ONCE (fp16 source, 16B copies) ----
    #pragma unroll
    for (int i = t; i < 128 * (K / 8); i += 256) {
        int row = i / (K / 8);
        int q   = i % (K / 8);
        uint4 vb = *(const uint4*)(Bh + (size_t)row * K + q * 8);
        Bs[row * SB + q * 4 + 0] = vb.x;
        Bs[row * SB + q * 4 + 1] = vb.y;
        Bs[row * SB + q * 4 + 2] = vb.z;
        Bs[row * SB + q * 4 + 3] = vb.w;
    }

    const int prow = t >> 3;
    const int pq   = t & 7;

    // ---- LDSM base addresses ----
    const uint32_t AsB = (uint32_t)__cvta_generic_to_shared(As);
    const uint32_t BsB = (uint32_t)__cvta_generic_to_shared(Bs);
    const uint32_t a_base = AsB +
        (((warpM * 32 + (lane & 15)) * 20 + (lane >> 4) * 4) << 2);
    uint32_t b_base[4];
    #pragma unroll
    for (int p = 0; p < 4; p++)
        b_base[p] = BsB +
            (((warpN * 64 + p * 16 + ((lane >> 4) << 3) + (lane & 7)) * SB +
              ((lane >> 3) & 1) * 4) << 2);

    const int ntile = (M + 127) / 128;

    for (int tile = blockIdx.x; tile < ntile; tile += GBLK) {
        const int row0 = tile * 128;

        float4 pa[4];
        auto loadA = [&](int c) {
            #pragma unroll
            for (int i = 0; i < 4; i++) {
                int row = prow + i * 32;
                int kk  = c * 32 + pq * 4;
                int gr  = row0 + row;
                if (FUSE && kk < 128) {
                    uint2 r = make_uint2(0u, 0u);
                    if (gr < M) r = *(const uint2*)(aggh + (size_t)gr * 128 + kk);
                    pa[i].x = __uint_as_float(r.x);
                    pa[i].y = __uint_as_float(r.y);
                } else {
                    float4 va = make_float4(0.f, 0.f, 0.f, 0.f);
                    if (gr < M) {
                        if (FUSE)
                            va = *(const float4*)(hdst + (size_t)gr * 128 + (kk - 128));
                        else
                            va = *(const float4*)(A + (size_t)gr * K + kk);
                    }
                    pa[i] = va;
                }
            }
        };
        auto storeA = [&](int c) {
            uint32_t* dstb = As + (c & 1) * (128 * 20);
            #pragma unroll
            for (int i = 0; i < 4; i++) {
                int row = prow + i * 32;
                int kk  = c * 32 + pq * 4;
                if (FUSE && kk < 128) {
                    dstb[row * 20 + pq * 2 + 0] = __float_as_uint(pa[i].x);
                    dstb[row * 20 + pq * 2 + 1] = __float_as_uint(pa[i].y);
                } else {
                    dstb[row * 20 + pq * 2 + 0] = pack_h2(pa[i].x, pa[i].y);
                    dstb[row * 20 + pq * 2 + 1] = pack_h2(pa[i].z, pa[i].w);
                }
            }
        };

        float acc[2][8][4];
        #pragma unroll
        for (int mt = 0; mt < 2; mt++)
            #pragma unroll
            for (int nt = 0; nt < 8; nt++)
                #pragma unroll
                for (int r = 0; r < 4; r++) acc[mt][nt][r] = 0.f;

        loadA(0);

        #pragma unroll
        for (int c = 0; c < NCH; c++) {
            storeA(c);
            __syncthreads();               // also covers Bs on first tile
            if (c + 1 < NCH) loadA(c + 1);

            const uint32_t abuf = a_base + ((c & 1) * (128 * 20) << 2);
            #pragma unroll
            for (int ks = 0; ks < 2; ks++) {
                uint32_t a[2][4], bf[4][4];
                ldsm_x4(a[0], abuf + (ks * 8 << 2));
                ldsm_x4(a[1], abuf + ((16 * 20 + ks * 8) << 2));
                #pragma unroll
                for (int p = 0; p < 4; p++)
                    ldsm_x4(bf[p], b_base[p] + ((c * 16 + ks * 8) << 2));
                #pragma unroll
                for (int mt = 0; mt < 2; mt++)
                    #pragma unroll
                    for (int nt = 0; nt < 8; nt++)
                        mma_f16(acc[mt][nt], a[mt],
                                bf[nt >> 1][(nt & 1) * 2], bf[nt >> 1][(nt & 1) * 2 + 1],
                                acc[mt][nt]);
            }
        }
        __syncthreads();

        #pragma unroll
        for (int nt = 0; nt < 8; nt++) {
            int cb = warpN * 64 + nt * 8 + 2 * tig;
            float b0 = __ldg(bias + cb);
            float b1 = __ldg(bias + cb + 1);
            #pragma unroll
            for (int mt = 0; mt < 2; mt++) {
                acc[mt][nt][0] = fmaxf(acc[mt][nt][0] + b0, 0.f);
                acc[mt][nt][1] = fmaxf(acc[mt][nt][1] + b1, 0.f);
                acc[mt][nt][2] = fmaxf(acc[mt][nt][2] + b0, 0.f);
                acc[mt][nt][3] = fmaxf(acc[mt][nt][3] + b1, 0.f);
            }
        }

        if (NORM) {
            float* C = (float*)Cv;
            if (t < 128) rowsq[t] = 0.f;
            __syncthreads();
            #pragma unroll
            for (int mt = 0; mt < 2; mt++) {
                float sA = 0.f, sB = 0.f;
                #pragma unroll
                for (int nt = 0; nt < 8; nt++) {
                    sA = fmaf(acc[mt][nt][0], acc[mt][nt][0], sA);
                    sA = fmaf(acc[mt][nt][1], acc[mt][nt][1], sA);
                    sB = fmaf(acc[mt][nt][2], acc[mt][nt][2], sB);
                    sB = fmaf(acc[mt][nt][3], acc[mt][nt][3], sB);
                }
                sA += __shfl_xor_sync(0xffffffffu, sA, 1);
                sA += __shfl_xor_sync(0xffffffffu, sA, 2);
                sB += __shfl_xor_sync(0xffffffffu, sB, 1);
                sB += __shfl_xor_sync(0xffffffffu, sB, 2);
                if (tig == 0) {
                    int lr = warpM * 32 + mt * 16 + gid;
                    atomicAdd(&rowsq[lr], sA);
                    atomicAdd(&rowsq[lr + 8], sB);
                }
            }
            __syncthreads();
            if (t < 128) {
                float nrm = sqrtf(rowsq[t]);
                rinv[t] = (nrm > 0.f) ? (1.f / nrm) : 1.f;
            }
            __syncthreads();
            #pragma unroll
            for (int mt = 0; mt < 2; mt++) {
                int lrA = warpM * 32 + mt * 16 + gid;
                int rA  = row0 + lrA;
                float sa = rinv[lrA];
                float sb = rinv[lrA + 8];
                #pragma unroll
                for (int nt = 0; nt < 8; nt++) {
                    int cb = warpN * 64 + nt * 8 + 2 * tig;
                    if (rA < M) {
                        float2 v = make_float2(acc[mt][nt][0] * sa, acc[mt][nt][1] * sa);
                        *(float2*)(C + (size_t)rA * 128 + cb) = v;
                    }
                    if (rA + 8 < M) {
                        float2 v = make_float2(acc[mt][nt][2] * sb, acc[mt][nt][3] * sb);
                        *(float2*)(C + (size_t)(rA + 8) * 128 + cb) = v;
                    }
                }
            }
            __syncthreads();   // rinv/rowsq safe before next tile
        } else {
            #pragma unroll
            for (int mt = 0; mt < 2; mt++) {
                int rA = row0 + warpM * 32 + mt * 16 + gid;
                #pragma unroll
                for (int nt = 0; nt < 8; nt++) {
                    int cb = warpN * 64 + nt * 8 + 2 * tig;
                    if (HALF_OUT) {
                        __half* C = (__half*)Cv;
                        if (rA < M) {
                            __half2 v = __floats2half2_rn(acc[mt][nt][0], acc[mt][nt][1]);
                            *(__half2*)(C + (size_t)rA * 128 + cb) = v;
                        }
                        if (rA + 8 < M) {
                            __half2 v = __floats2half2_rn(acc[mt][nt][2], acc[mt][nt][3]);
                            *(__half2*)(C + (size_t)(rA + 8) * 128 + cb) = v;
                        }
                    } else {
                        float* C = (float*)Cv;
                        if (rA < M) {
                            float2 v = make_float2(acc[mt][nt][0], acc[mt][nt][1]);
                            *(float2*)(C + (size_t)rA * 128 + cb) = v;
                        }
                        if (rA + 8 < M) {
                            float2 v = make_float2(acc[mt][nt][2], acc[mt][nt][3]);
                            *(float2*)(C + (size_t)(rA + 8) * 128 + cb) = v;
                        }
                    }
                }
            }
        }
    }
}

// ---------------- slotted bucketing: one pass, no hist/scan ----------------
__global__ void __launch_bounds__(256)
bucket_kernel(const int* __restrict__ src,
              const int* __restrict__ dst,
              const float* __restrict__ w)
{
    int i = blockIdx.x * 256 + threadIdx.x;
    if (i * 4 >= NE) return;
    int4   s4 = ((const int4*)src)[i];
    int4   d4 = ((const int4*)dst)[i];
    float4 w4 = ((const float4*)w)[i];
    int p0 = atomicAdd(&g_cur[d4.x], 1);
    int p1 = atomicAdd(&g_cur[d4.y], 1);
    int p2 = atomicAdd(&g_cur[d4.z], 1);
    int p3 = atomicAdd(&g_cur[d4.w], 1);
    if (p0 < SLOTS) g_edge[(size_t)d4.x * SLOTS + p0] =
        (uint64_t)(uint32_t)s4.x | ((uint64_t)__float_as_uint(w4.x) << 32);
    if (p1 < SLOTS) g_edge[(size_t)d4.y * SLOTS + p1] =
        (uint64_t)(uint32_t)s4.y | ((uint64_t)__float_as_uint(w4.y) << 32);
    if (p2 < SLOTS) g_edge[(size_t)d4.z * SLOTS + p2] =
        (uint64_t)(uint32_t)s4.z | ((uint64_t)__float_as_uint(w4.z) << 32);
    if (p3 < SLOTS) g_edge[(size_t)d4.w * SLOTS + p3] =
        (uint64_t)(uint32_t)s4.w | ((uint64_t)__float_as_uint(w4.w) << 32);
}

// ---------------- aggregation: warp per dst, fp16 gather, fp16 output -----------
__global__ void __launch_bounds__(256)
aggregate_kernel()
{
    int d = blockIdx.x * 8 + (threadIdx.x >> 5);
    if (d >= N_DST) return;
    int lane = threadIdx.x & 31;
    const uint64_t* eb = g_edge + (size_t)d * SLOTS;
    int cnt = g_cur[d];
    if (cnt > SLOTS) cnt = SLOTS;

    float4 acc = make_float4(0.f, 0.f, 0.f, 0.f);
    float ws = 0.f;
    int i = 0;
    for (; i + 3 < cnt; i += 4) {
        uint64_t e0 = eb[i],     e1 = eb[i + 1];
        uint64_t e2 = eb[i + 2], e3 = eb[i + 3];
        int   s0 = (int)(uint32_t)e0, s1 = (int)(uint32_t)e1;
        int   s2 = (int)(uint32_t)e2, s3 = (int)(uint32_t)e3;
        float w0 = __uint_as_float((uint32_t)(e0 >> 32));
        float w1 = __uint_as_float((uint32_t)(e1 >> 32));
        float w2 = __uint_as_float((uint32_t)(e2 >> 32));
        float w3 = __uint_as_float((uint32_t)(e3 >> 32));
        uint2 r0 = ((const uint2*)(g_nh + (size_t)s0 * 128))[lane];
        uint2 r1 = ((const uint2*)(g_nh + (size_t)s1 * 128))[lane];
        uint2 r2 = ((const uint2*)(g_nh + (size_t)s2 * 128))[lane];
        uint2 r3 = ((const uint2*)(g_nh + (size_t)s3 * 128))[lane];
        float2 a0 = __half22float2(*(__half2*)&r0.x), b0 = __half22float2(*(__half2*)&r0.y);
        float2 a1 = __half22float2(*(__half2*)&r1.x), b1 = __half22float2(*(__half2*)&r1.y);
        float2 a2 = __half22float2(*(__half2*)&r2.x), b2 = __half22float2(*(__half2*)&r2.y);
        float2 a3 = __half22float2(*(__half2*)&r3.x), b3 = __half22float2(*(__half2*)&r3.y);
        acc.x = fmaf(a0.x, w0, acc.x); acc.y = fmaf(a0.y, w0, acc.y);
        acc.z = fmaf(b0.x, w0, acc.z); acc.w = fmaf(b0.y, w0, acc.w);
        acc.x = fmaf(a1.x, w1, acc.x); acc.y = fmaf(a1.y, w1, acc.y);
        acc.z = fmaf(b1.x, w1, acc.z); acc.w = fmaf(b1.y, w1, acc.w);
        acc.x = fmaf(a2.x, w2, acc.x); acc.y = fmaf(a2.y, w2, acc.y);
        acc.z = fmaf(b2.x, w2, acc.z); acc.w = fmaf(b2.y, w2, acc.w);
        acc.x = fmaf(a3.x, w3, acc.x); acc.y = fmaf(a3.y, w3, acc.y);
        acc.z = fmaf(b3.x, w3, acc.z); acc.w = fmaf(b3.y, w3, acc.w);
        ws += (w0 + w1) + (w2 + w3);
    }
    for (; i < cnt; i++) {
        uint64_t e0 = eb[i];
        int   s0 = (int)(uint32_t)e0;
        float w0 = __uint_as_float((uint32_t)(e0 >> 32));
        uint2 r0 = ((const uint2*)(g_nh + (size_t)s0 * 128))[lane];
        float2 a0 = __half22float2(*(__half2*)&r0.x), b0 = __half22float2(*(__half2*)&r0.y);
        acc.x = fmaf(a0.x, w0, acc.x); acc.y = fmaf(a0.y, w0, acc.y);
        acc.z = fmaf(b0.x, w0, acc.z); acc.w = fmaf(b0.y, w0, acc.w);
        ws += w0;
    }
    float inv = 1.f / fmaxf(ws, 1.f);
    uint2 o;
    o.x = pack_h2(acc.x * inv, acc.y * inv);
    o.y = pack_h2(acc.z * inv, acc.w * inv);
    ((uint2*)(g_aggh + (size_t)d * 128))[lane] = o;
}

extern "C" void kernel_launch(void* const* d_in, const int* in_sizes, int n_in,
                              void* d_out, int out_size)
{
    const float* h_src   = (const float*)d_in[0];
    const float* h_dst   = (const float*)d_in[1];
    const float* weights = (const float*)d_in[2];
    const float* Qw      = (const float*)d_in[3];
    const float* Qb      = (const float*)d_in[4];
    const float* Ww      = (const float*)d_in[5];
    const float* Wb      = (const float*)d_in[6];
    const int*   src     = (const int*)d_in[7];
    const int*   dst     = (const int*)d_in[8];
    float*       out     = (float*)d_out;

    const int smem1 = GEMM_SMEM_WORDS(128) * 4;
    const int smem2 = GEMM_SMEM_WORDS(256) * 4;

    static void *p_nh = nullptr, *p_aggh = nullptr, *p_qh = nullptr, *p_wh = nullptr;
    static int  *p_cur = nullptr;
    static cudaStream_t s2 = nullptr;
    static cudaEvent_t ev_fork = nullptr, ev_g1 = nullptr, ev_join = nullptr;
    if (!p_nh) {
        cudaGetSymbolAddress(&p_nh,          g_nh);
        cudaGetSymbolAddress(&p_aggh,        g_aggh);
        cudaGetSymbolAddress(&p_qh,          g_qh);
        cudaGetSymbolAddress(&p_wh,          g_wh);
        cudaGetSymbolAddress((void**)&p_cur, g_cur);
        cudaFuncSetAttribute(gemm_tc<128, false, false, true>,
                             cudaFuncAttributeMaxDynamicSharedMemorySize, smem1);
        cudaFuncSetAttribute(gemm_tc<256, true, true, false>,
                             cudaFuncAttributeMaxDynamicSharedMemorySize, smem2);
        cudaStreamCreateWithFlags(&s2, cudaStreamNonBlocking);
        cudaEventCreateWithFlags(&ev_fork, cudaEventDisableTiming);
        cudaEventCreateWithFlags(&ev_g1,   cudaEventDisableTiming);
        cudaEventCreateWithFlags(&ev_join, cudaEventDisableTiming);
    }

    // ---- fork: slotted bucketing on s2, weight-convert + gemm1 on default ----
    cudaEventRecord(ev_fork, 0);
    cudaStreamWaitEvent(s2, ev_fork, 0);

    cudaMemsetAsync(p_cur, 0, N_DST * sizeof(int), s2);
    bucket_kernel<<<(NE / 4 + 255) / 256, 256, 0, s2>>>(src, dst, weights);

    convert_w<<<48, 256>>>(Qw, Ww);
    gemm_tc<128, false, false, true><<<GBLK, 256, smem1>>>(
        h_src, nullptr, nullptr, (const __half*)p_qh, Qb, p_nh, N_SRC);
    cudaEventRecord(ev_g1, 0);

    // ---- s2: aggregate needs g_nh + buckets ----
    cudaStreamWaitEvent(s2, ev_g1, 0);
    aggregate_kernel<<<(N_DST + 7) / 8, 256, 0, s2>>>();
    cudaEventRecord(ev_join, s2);

    // gemm2 on default stream after aggregate
    cudaStreamWaitEvent(0, ev_join, 0);
    gemm_tc<256, true, true, false><<<GBLK, 256, smem2>>>(
        nullptr, (const __half*)p_aggh, h_dst, (const __half*)p_wh, Wb, out, N_DST);
}